// round 14
// baseline (speedup 1.0000x reference)
#include <cuda_runtime.h>

// VectorQuantizer: z [B,64] f32, codebook [1024,64] f32
// out = concat( z_q_st [B*64], vq_loss [1], indices-as-float [B] )

typedef unsigned long long u64;

#define K_CODES 1024
#define D 64
#define THREADS 128
#define RPT 4                       // rows per thread
#define ROWS_CTA (THREADS*RPT)      // 512
#define CHUNK 256                   // codes staged in smem per pass
#define NCHUNK (K_CODES/CHUNK)
#define KB 4                        // codes per register tile (16 indep FFMA2 chains)

__device__ double   g_loss;
__device__ unsigned g_done;
__device__ float    g_c2[K_CODES];  // per-code squared norm (pairwise tree)

static __device__ __forceinline__ u64 pack2(float x, float y) {
    u64 r; asm("mov.b64 %0,{%1,%2};" : "=l"(r) : "f"(x), "f"(y)); return r;
}
static __device__ __forceinline__ void unpack2(u64 v, float& x, float& y) {
    asm("mov.b64 {%0,%1},%2;" : "=f"(x), "=f"(y) : "l"(v));
}
static __device__ __forceinline__ u64 ffma2(u64 a, u64 b, u64 c) {
    u64 d; asm("fma.rn.f32x2 %0,%1,%2,%3;" : "=l"(d) : "l"(a), "l"(b), "l"(c)); return d;
}

// Prep: c2 (pairwise tree, bitwise stable since R1), zero loss + done counter.
__global__ void vq_prep(const float* __restrict__ cb) {
    __shared__ float s[D];
    int k = blockIdx.x, d = threadIdx.x;
    float v = cb[k * D + d];
    s[d] = v * v;
    __syncthreads();
#pragma unroll
    for (int off = D / 2; off >= 1; off >>= 1) {
        if (d < off) s[d] = s[d] + s[d + off];
        __syncthreads();
    }
    if (d == 0) {
        g_c2[k] = s[0];
        if (k == 0) { g_loss = 0.0; g_done = 0u; }
    }
}

// z2 for one row held as packed pairs: reproduces the reference pairwise tree bitwise.
static __device__ __forceinline__ float z2_of(const u64* zp) {
    float s[32];
#pragma unroll
    for (int i = 0; i < 16; i++) {
        float a, b, c, d;
        unpack2(zp[2 * i],     a, b);
        unpack2(zp[2 * i + 1], c, d);
        s[2 * i]     = a * a + b * b;
        s[2 * i + 1] = c * c + d * d;
    }
#pragma unroll
    for (int off = 16; off >= 1; off >>= 1)
#pragma unroll
        for (int i = 0; i < off; i++) s[i] = s[i] + s[i + off];
    return s[0];
}

__global__ void __launch_bounds__(THREADS, 2)
vq_main(const float* __restrict__ z, const float* __restrict__ cb,
        float* __restrict__ out, int B, int out_size) {
    extern __shared__ float sm[];
    float* s_c  = sm;               // [CHUNK][D] row-major codebook chunk
    float* s_c2 = sm + CHUNK * D;   // [1024] all c2 (staged once)

    const int t = threadIdx.x;
    const long base = (long)blockIdx.x * ROWS_CTA;

    // Load 4 z rows packed as {z_2i, z_2i+1} pairs (one-time packing)
    u64 zp[RPT][D / 2];
#pragma unroll
    for (int q = 0; q < RPT; q++) {
        const float4* a4 = (const float4*)(z + (base + q * THREADS + t) * D);
#pragma unroll
        for (int i = 0; i < D / 4; i++) {
            float4 a = a4[i];
            zp[q][2 * i + 0] = pack2(a.x, a.y);
            zp[q][2 * i + 1] = pack2(a.z, a.w);
        }
    }
    float z2v[RPT];
#pragma unroll
    for (int q = 0; q < RPT; q++) z2v[q] = z2_of(zp[q]);

    // stage all c2 once
#pragma unroll
    for (int i = t; i < K_CODES; i += THREADS) s_c2[i] = g_c2[i];

    float mv[RPT];
    int   mi[RPT];
#pragma unroll
    for (int q = 0; q < RPT; q++) { mv[q] = 3.402823466e38f; mi[q] = 0; }

    for (int ch = 0; ch < NCHUNK; ++ch) {
        __syncthreads();
        // Stage codebook chunk row-major straight from global (coalesced float4)
        {
            const float4* src = (const float4*)(cb + (size_t)ch * CHUNK * D);
            float4* dst = (float4*)s_c;
#pragma unroll 8
            for (int i = t; i < CHUNK * D / 4; i += THREADS) dst[i] = src[i];
        }
        __syncthreads();

        const int kbase = ch * CHUNK;
        for (int kb = 0; kb < CHUNK; kb += KB) {
            u64 acc[RPT][KB];
#pragma unroll
            for (int q = 0; q < RPT; q++)
#pragma unroll
                for (int j = 0; j < KB; j++) acc[q][j] = 0ull;

            // lane0 accumulates even dims, lane1 odd dims (bitwise same as R10)
#pragma unroll
            for (int i = 0; i < D / 4; i++) {
                ulonglong2 c[KB];
#pragma unroll
                for (int j = 0; j < KB; j++)
                    c[j] = *(const ulonglong2*)(s_c + (size_t)(kb + j) * D + 4 * i);
#pragma unroll
                for (int q = 0; q < RPT; q++) {
                    u64 z0 = zp[q][2 * i], z1 = zp[q][2 * i + 1];
#pragma unroll
                    for (int j = 0; j < KB; j++) {
                        acc[q][j] = ffma2(z0, c[j].x, acc[q][j]);
                        acc[q][j] = ffma2(z1, c[j].y, acc[q][j]);
                    }
                }
            }
#pragma unroll
            for (int j = 0; j < KB; j++) {
                int k = kbase + kb + j;
                float c2s = s_c2[k];   // FIXED: global index (R12 bug was s_c2[kb+j])
#pragma unroll
                for (int q = 0; q < RPT; q++) {
                    float e, o;
                    unpack2(acc[q][j], e, o);
                    float dv = fmaf(-2.0f, e + o, z2v[q]) + c2s;  // 2*cross exact
                    if (dv < mv[q]) { mv[q] = dv; mi[q] = k; }    // strict < => first idx
                }
            }
        }
    }

    // Epilogue: gather z_q, write out, loss partials in double
    double lacc = 0.0;
#pragma unroll
    for (int q = 0; q < RPT; q++) {
        const long row = base + q * THREADS + t;
        const float4* qv = (const float4*)(cb + (size_t)mi[q] * D);
        float4* o = (float4*)(out + row * D);
#pragma unroll
        for (int i = 0; i < D / 4; i++) {
            float4 a = qv[i];
            float x, y, u, w, d;
            unpack2(zp[q][2 * i],     x, y);
            unpack2(zp[q][2 * i + 1], u, w);
            d = a.x - x; lacc += (double)(d * d);
            d = a.y - y; lacc += (double)(d * d);
            d = a.z - u; lacc += (double)(d * d);
            d = a.w - w; lacc += (double)(d * d);
            o[i] = a;
        }
    }

    if ((long)out_size >= (long)B * D + 1 + B) {
        const long iofs = (long)B * D + 1;
#pragma unroll
        for (int q = 0; q < RPT; q++)
            out[iofs + base + q * THREADS + t] = (float)mi[q];
    }

    // block-reduce loss partials (reuse smem), one atomic per CTA
    __syncthreads();
    double* sd = (double*)sm;
    sd[t] = lacc;
    __syncthreads();
#pragma unroll
    for (int off = THREADS / 2; off >= 1; off >>= 1) {
        if (t < off) sd[t] += sd[t + off];
        __syncthreads();
    }
    if (t == 0) {
        atomicAdd(&g_loss, sd[0]);
        __threadfence();
        unsigned v = atomicAdd(&g_done, 1u);
        if (v == gridDim.x - 1) {       // last CTA finalizes loss
            g_done = 0u;
            if ((long)out_size >= (long)B * D + 1) {
                float m = (float)(g_loss / (double)((long)B * D));
                out[(size_t)B * D] = m + 0.25f * m;
            }
        }
    }
}

extern "C" void kernel_launch(void* const* d_in, const int* in_sizes, int n_in,
                              void* d_out, int out_size) {
    const float* z  = (const float*)d_in[0];
    const float* cb = (const float*)d_in[1];
    float* out = (float*)d_out;
    const int B = in_sizes[0] / D;

    const size_t smem = (size_t)CHUNK * D * sizeof(float) + K_CODES * sizeof(float);
    cudaFuncSetAttribute(vq_main, cudaFuncAttributeMaxDynamicSharedMemorySize, (int)smem);

    vq_prep<<<K_CODES, D>>>(cb);
    vq_main<<<B / ROWS_CTA, THREADS, smem>>>(z, cb, out, B, out_size);
}